// round 1
// baseline (speedup 1.0000x reference)
#include <cuda_runtime.h>
#include <cuda_bf16.h>
#include <math.h>

// Problem constants
#define BATCH 2
#define SEQ   2048
#define DIM   2048
#define NH    16
#define NKV   8
#define HD    128
#define HALF_HD 64
#define NREP  2

#define M_ROWS (BATCH * SEQ)          // 4096

// ---------------- scratch (static device globals; no allocation) ----------------
__device__ float g_qlin[(size_t)M_ROWS * DIM];                 // x @ wq^T  [4096, 2048]
__device__ float g_klin[(size_t)M_ROWS * (NKV * HD)];          // [4096, 1024]
__device__ float g_vlin[(size_t)M_ROWS * (NKV * HD)];          // [4096, 1024]
__device__ float g_Q[(size_t)BATCH * NH  * SEQ * HD];          // [B,H,S,D] roped
__device__ float g_K[(size_t)BATCH * NKV * SEQ * HD];          // [B,KV,S,D] roped
__device__ float g_V[(size_t)BATCH * NKV * SEQ * HD];          // [B,KV,S,D]
__device__ float g_scores[(size_t)BATCH * NH * SEQ * SEQ];     // 512 MB probs scratch
__device__ float g_attn_t[(size_t)M_ROWS * DIM];               // [B*S, H*D]
__device__ float g_cosT[SEQ * HALF_HD];
__device__ float g_sinT[SEQ * HALF_HD];

// ---------------- RoPE table: angle in fp32 (matches reference), cos/sin in fp64 ----------------
__global__ void rope_table_kernel(float* cosT, float* sinT) {
    int s = blockIdx.x;
    int i = threadIdx.x;                       // 0..63
    float inv = (float)pow(10000.0, -(double)(2 * i) / (double)HD);
    float ang = (float)s * inv;                // fp32 product, same as jnp.outer in fp32
    double a = (double)ang;
    cosT[s * HALF_HD + i] = (float)cos(a);
    sinT[s * HALF_HD + i] = (float)sin(a);
}

// ---------------- RoPE apply + transpose to [B,H,S,D] ----------------
__global__ void rope_q_kernel(const float* __restrict__ qlin,
                              const float* __restrict__ cosT,
                              const float* __restrict__ sinT,
                              float* __restrict__ Q) {
    long idx = (long)blockIdx.x * blockDim.x + threadIdx.x;     // B*S*NH*64
    if (idx >= (long)BATCH * SEQ * NH * HALF_HD) return;
    int i = idx & (HALF_HD - 1);
    long t = idx >> 6;
    int h = t & (NH - 1); t >>= 4;
    int s = t & (SEQ - 1);
    int b = (int)(t >> 11);
    const float* src = qlin + ((long)(b * SEQ + s)) * DIM + h * HD + 2 * i;
    float xr = src[0], xi = src[1];
    float c = cosT[s * HALF_HD + i], sn = sinT[s * HALF_HD + i];
    float* dst = Q + (((long)(b * NH + h) * SEQ + s)) * HD + 2 * i;
    dst[0] = xr * c - xi * sn;
    dst[1] = xr * sn + xi * c;
}

__global__ void rope_k_kernel(const float* __restrict__ klin,
                              const float* __restrict__ cosT,
                              const float* __restrict__ sinT,
                              float* __restrict__ K) {
    long idx = (long)blockIdx.x * blockDim.x + threadIdx.x;     // B*S*NKV*64
    if (idx >= (long)BATCH * SEQ * NKV * HALF_HD) return;
    int i = idx & (HALF_HD - 1);
    long t = idx >> 6;
    int h = t & (NKV - 1); t >>= 3;
    int s = t & (SEQ - 1);
    int b = (int)(t >> 11);
    const float* src = klin + ((long)(b * SEQ + s)) * (NKV * HD) + h * HD + 2 * i;
    float xr = src[0], xi = src[1];
    float c = cosT[s * HALF_HD + i], sn = sinT[s * HALF_HD + i];
    float* dst = K + (((long)(b * NKV + h) * SEQ + s)) * HD + 2 * i;
    dst[0] = xr * c - xi * sn;
    dst[1] = xr * sn + xi * c;
}

__global__ void v_transpose_kernel(const float* __restrict__ vlin,
                                   float* __restrict__ V) {
    long idx = (long)blockIdx.x * blockDim.x + threadIdx.x;     // B*S*NKV*128
    if (idx >= (long)BATCH * SEQ * NKV * HD) return;
    int d = idx & (HD - 1);
    long t = idx >> 7;
    int h = t & (NKV - 1); t >>= 3;
    int s = t & (SEQ - 1);
    int b = (int)(t >> 11);
    V[(((long)(b * NKV + h) * SEQ + s)) * HD + d] =
        vlin[((long)(b * SEQ + s)) * (NKV * HD) + h * HD + d];
}

// ---------------- generic tiled SGEMM ----------------
// C[M,N] = alpha * A[M,K] @ op(B); TRANSB: B is [N,K] row-major; else B is [K,N] row-major.
// Batched via blockIdx.z: zb = z/zdiv, zh = z%zdiv.
//   A += zb*sA0 + zh*sA1; B += zb*sB0 + (zh/brep)*sB1; C += zb*sC0 + zh*sC1
// MODE: 0 normal; 1 causal (skip tiles fully above diagonal, M==N==SEQ rows/cols);
//       2 pv (limit K loop to the tile's max row index + 1).
#define BM 64
#define BN 64
#define BKT 16

template <bool TRANSB, int MODE>
__global__ __launch_bounds__(256) void sgemm_kernel(
    const float* __restrict__ A, int lda,
    const float* __restrict__ B, int ldb,
    float* __restrict__ C, int ldc,
    int M, int N, int K, float alpha,
    long sA0, long sA1, long sB0, long sB1, long sC0, long sC1,
    int zdiv, int brep)
{
    int z = blockIdx.z;
    int zb = z / zdiv, zh = z % zdiv;
    A += zb * sA0 + (long)zh * sA1;
    B += zb * sB0 + (long)(zh / brep) * sB1;
    C += zb * sC0 + (long)zh * sC1;

    int m0 = blockIdx.y * BM;
    int n0 = blockIdx.x * BN;
    if (MODE == 1 && n0 > m0 + BM - 1) return;   // fully-masked causal tile
    int kEnd = K;
    if (MODE == 2) kEnd = min(K, m0 + BM);

    __shared__ float As[BKT][BM];
    __shared__ float Bs[BKT][BN];

    int tid = threadIdx.x;             // 0..255
    int tx = tid & 15, ty = tid >> 4;  // 16x16
    int lk = tid & 15;                 // k slot for loads
    int lm = tid >> 4;                 // row base for loads

    float acc[4][4] = {};

    for (int k0 = 0; k0 < kEnd; k0 += BKT) {
#pragma unroll
        for (int j = 0; j < 4; j++)
            As[lk][lm + 16 * j] = A[(long)(m0 + lm + 16 * j) * lda + k0 + lk];
        if (TRANSB) {
#pragma unroll
            for (int j = 0; j < 4; j++)
                Bs[lk][lm + 16 * j] = B[(long)(n0 + lm + 16 * j) * ldb + k0 + lk];
        } else {
#pragma unroll
            for (int j = 0; j < 4; j++) {
                int idx = tid + 256 * j;
                int kk = idx >> 6, nn = idx & 63;
                Bs[kk][nn] = B[(long)(k0 + kk) * ldb + n0 + nn];
            }
        }
        __syncthreads();
#pragma unroll
        for (int k = 0; k < BKT; k++) {
            float a[4], b[4];
#pragma unroll
            for (int i = 0; i < 4; i++) a[i] = As[k][ty * 4 + i];
#pragma unroll
            for (int j = 0; j < 4; j++) b[j] = Bs[k][tx * 4 + j];
#pragma unroll
            for (int i = 0; i < 4; i++)
#pragma unroll
                for (int j = 0; j < 4; j++)
                    acc[i][j] += a[i] * b[j];
        }
        __syncthreads();
    }

#pragma unroll
    for (int i = 0; i < 4; i++)
#pragma unroll
        for (int j = 0; j < 4; j++)
            C[(long)(m0 + ty * 4 + i) * ldc + n0 + tx * 4 + j] = alpha * acc[i][j];
}

// ---------------- causal softmax, one block per row ----------------
__global__ __launch_bounds__(256) void softmax_causal_kernel(float* __restrict__ scores) {
    long row = blockIdx.x;                       // 0 .. B*NH*SEQ-1
    int qi = (int)(row & (SEQ - 1));
    float* p = scores + (row << 11);             // row * 2048
    int len = qi + 1;
    int tid = threadIdx.x;

    float v[8];
    int cnt = 0;
    float m = -1e30f;
    for (int j = tid; j < len; j += 256) {
        float x = p[j];
        v[cnt++] = x;
        m = fmaxf(m, x);
    }
    __shared__ float sred[8];
#pragma unroll
    for (int o = 16; o > 0; o >>= 1) m = fmaxf(m, __shfl_xor_sync(0xffffffffu, m, o));
    if ((tid & 31) == 0) sred[tid >> 5] = m;
    __syncthreads();
    float bm = fmaxf(fmaxf(fmaxf(sred[0], sred[1]), fmaxf(sred[2], sred[3])),
                     fmaxf(fmaxf(sred[4], sred[5]), fmaxf(sred[6], sred[7])));
    __syncthreads();

    float s = 0.f;
    for (int c = 0; c < cnt; c++) { v[c] = expf(v[c] - bm); s += v[c]; }
#pragma unroll
    for (int o = 16; o > 0; o >>= 1) s += __shfl_xor_sync(0xffffffffu, s, o);
    if ((tid & 31) == 0) sred[tid >> 5] = s;
    __syncthreads();
    float bs = sred[0] + sred[1] + sred[2] + sred[3] + sred[4] + sred[5] + sred[6] + sred[7];
    float inv = 1.0f / bs;

    int c2 = 0;
    for (int j = tid; j < SEQ; j += 256) {
        float o = 0.f;
        if (j < len) o = v[c2++] * inv;
        p[j] = o;
    }
}

// ---------------- launch ----------------
extern "C" void kernel_launch(void* const* d_in, const int* in_sizes, int n_in,
                              void* d_out, int out_size) {
    const float* x  = (const float*)d_in[0];
    const float* wq = (const float*)d_in[1];
    const float* wk = (const float*)d_in[2];
    const float* wv = (const float*)d_in[3];
    const float* wo = (const float*)d_in[4];
    float* out = (float*)d_out;

    float* qlin; cudaGetSymbolAddress((void**)&qlin, g_qlin);
    float* klin; cudaGetSymbolAddress((void**)&klin, g_klin);
    float* vlin; cudaGetSymbolAddress((void**)&vlin, g_vlin);
    float* Q;    cudaGetSymbolAddress((void**)&Q,    g_Q);
    float* Kd;   cudaGetSymbolAddress((void**)&Kd,   g_K);
    float* V;    cudaGetSymbolAddress((void**)&V,    g_V);
    float* sc;   cudaGetSymbolAddress((void**)&sc,   g_scores);
    float* at;   cudaGetSymbolAddress((void**)&at,   g_attn_t);
    float* cT;   cudaGetSymbolAddress((void**)&cT,   g_cosT);
    float* sT;   cudaGetSymbolAddress((void**)&sT,   g_sinT);

    // 1) RoPE table
    rope_table_kernel<<<SEQ, HALF_HD>>>(cT, sT);

    // 2) QKV projections: lin = x @ w^T
    sgemm_kernel<true, 0><<<dim3(DIM / BN, M_ROWS / BM, 1), 256>>>(
        x, DIM, wq, DIM, qlin, DIM, M_ROWS, DIM, DIM, 1.f,
        0, 0, 0, 0, 0, 0, 1, 1);
    sgemm_kernel<true, 0><<<dim3((NKV * HD) / BN, M_ROWS / BM, 1), 256>>>(
        x, DIM, wk, DIM, klin, NKV * HD, M_ROWS, NKV * HD, DIM, 1.f,
        0, 0, 0, 0, 0, 0, 1, 1);
    sgemm_kernel<true, 0><<<dim3((NKV * HD) / BN, M_ROWS / BM, 1), 256>>>(
        x, DIM, wv, DIM, vlin, NKV * HD, M_ROWS, NKV * HD, DIM, 1.f,
        0, 0, 0, 0, 0, 0, 1, 1);

    // 3) RoPE + transpose
    {
        long nq = (long)BATCH * SEQ * NH * HALF_HD;
        rope_q_kernel<<<(unsigned)((nq + 255) / 256), 256>>>(qlin, cT, sT, Q);
        long nk = (long)BATCH * SEQ * NKV * HALF_HD;
        rope_k_kernel<<<(unsigned)((nk + 255) / 256), 256>>>(klin, cT, sT, Kd);
        long nv = (long)BATCH * SEQ * NKV * HD;
        v_transpose_kernel<<<(unsigned)((nv + 255) / 256), 256>>>(vlin, V);
    }

    // 4) scores = Q @ K^T * scale   (batched over z = b*NH+h, causal tile skip)
    {
        const float scale = 0.088388347648318447f;   // 1/sqrt(128)
        long sA1 = (long)SEQ * HD, sA0 = (long)NH * SEQ * HD;
        long sB1 = (long)SEQ * HD, sB0 = (long)NKV * SEQ * HD;
        long sC1 = (long)SEQ * SEQ, sC0 = (long)NH * SEQ * SEQ;
        sgemm_kernel<true, 1><<<dim3(SEQ / BN, SEQ / BM, BATCH * NH), 256>>>(
            Q, HD, Kd, HD, sc, SEQ, SEQ, SEQ, HD, scale,
            sA0, sA1, sB0, sB1, sC0, sC1, NH, NREP);
    }

    // 5) causal softmax (writes zeros above diagonal)
    softmax_causal_kernel<<<BATCH * NH * SEQ, 256>>>(sc);

    // 6) attn_t[b*S+s, h*HD+d] = probs @ V   (K-loop clipped by causality)
    {
        long sA1 = (long)SEQ * SEQ, sA0 = (long)NH * SEQ * SEQ;
        long sB1 = (long)SEQ * HD,  sB0 = (long)NKV * SEQ * HD;
        long sC1 = (long)HD,        sC0 = (long)SEQ * DIM;
        sgemm_kernel<false, 2><<<dim3(HD / BN, SEQ / BM, BATCH * NH), 256>>>(
            sc, SEQ, V, HD, at, DIM, SEQ, HD, SEQ, 1.f,
            sA0, sA1, sB0, sB1, sC0, sC1, NH, NREP);
    }

    // 7) out = attn_t @ wo^T
    sgemm_kernel<true, 0><<<dim3(DIM / BN, M_ROWS / BM, 1), 256>>>(
        at, DIM, wo, DIM, out, DIM, M_ROWS, DIM, DIM, 1.f,
        0, 0, 0, 0, 0, 0, 1, 1);

    (void)in_sizes; (void)n_in; (void)out_size;
}

// round 4
// speedup vs baseline: 4.8917x; 4.8917x over previous
#include <cuda_runtime.h>
#include <cuda_bf16.h>
#include <cstdint>
#include <math.h>

// ---------------- problem constants ----------------
#define BATCH 2
#define SEQ   2048
#define DIM   2048
#define NH    16
#define NKV   8
#define HD    128
#define HALF_HD 64
#define NREP  2
#define M_ROWS (BATCH * SEQ)          // 4096

// ---------------- scratch (static device globals; no allocation) ----------------
__device__ float g_qlin[(size_t)M_ROWS * DIM];
__device__ float g_klin[(size_t)M_ROWS * (NKV * HD)];
__device__ float g_vlin[(size_t)M_ROWS * (NKV * HD)];
__device__ float g_Q[(size_t)BATCH * NH  * SEQ * HD];          // [B,H,S,D]
__device__ float g_K[(size_t)BATCH * NKV * SEQ * HD];          // [B,KV,S,D]
__device__ float g_Vt[(size_t)BATCH * NKV * HD * SEQ];         // [B,KV,D,S]
__device__ float g_scores[(size_t)BATCH * NH * SEQ * SEQ];     // probs scratch
__device__ float g_attn_t[(size_t)M_ROWS * DIM];               // [B*S, H*D]
__device__ float g_cosT[SEQ * HALF_HD];
__device__ float g_sinT[SEQ * HALF_HD];

// ---------------- PTX helpers ----------------
__device__ __forceinline__ uint32_t smem_u32(const void* p) {
    uint32_t a;
    asm("{ .reg .u64 t; cvta.to.shared.u64 t, %1; cvt.u32.u64 %0, t; }" : "=r"(a) : "l"(p));
    return a;
}
__device__ __forceinline__ uint32_t f2tf32(float x) {
    uint32_t r;
    asm("cvt.rna.tf32.f32 %0, %1;" : "=r"(r) : "f"(x));
    return r;
}
__device__ __forceinline__ void cp_async16(uint32_t saddr, const void* g) {
    asm volatile("cp.async.cg.shared.global [%0], [%1], 16;" :: "r"(saddr), "l"(g));
}
#define CP_COMMIT() asm volatile("cp.async.commit_group;" ::: "memory")
#define CP_WAIT1()  asm volatile("cp.async.wait_group 1;" ::: "memory")

__device__ __forceinline__ void mma_tf32(float* c, const uint32_t* a, const uint32_t* b) {
    asm volatile("mma.sync.aligned.m16n8k8.row.col.f32.tf32.tf32.f32 "
        "{%0,%1,%2,%3}, {%4,%5,%6,%7}, {%8,%9}, {%0,%1,%2,%3};"
        : "+f"(c[0]), "+f"(c[1]), "+f"(c[2]), "+f"(c[3])
        : "r"(a[0]), "r"(a[1]), "r"(a[2]), "r"(a[3]), "r"(b[0]), "r"(b[1]));
}

// ---------------- tf32 mma.sync GEMM ----------------
// C[M,N] = alpha * A[M,K] @ B[N,K]^T (both K-major fp32, rounded to tf32 at fragment load)
// MODE 0: plain; 1: causal tile-skip; 2: PV (K clipped to m0+TBM)
#define TBM 128
#define TBN 128
#define TBK 16
#define AROW 20                      // 16 + 4 pad floats

template <int MODE>
__global__ __launch_bounds__(256) void mma_gemm(
    const float* __restrict__ A, int lda,
    const float* __restrict__ B, int ldb,
    float* __restrict__ C, int ldc,
    int K, float alpha,
    long sA0, long sA1, long sB0, long sB1, long sC0, long sC1,
    int zdiv, int brep)
{
    int z = blockIdx.z;
    int zb = z / zdiv, zh = z % zdiv;
    A += zb * sA0 + (long)zh * sA1;
    B += zb * sB0 + (long)(zh / brep) * sB1;
    C += zb * sC0 + (long)zh * sC1;

    int m0 = blockIdx.y * TBM;
    int n0 = blockIdx.x * TBN;
    if (MODE == 1 && n0 > m0) return;            // fully-masked causal tile
    int kEnd = (MODE == 2) ? min(K, m0 + TBM) : K;
    int nch = kEnd / TBK;                        // >= 8 always here

    __shared__ float sA[2][TBM][AROW];
    __shared__ float sB[2][TBN][AROW];

    int tid = threadIdx.x;
    int wid = tid >> 5;
    int lane = tid & 31;
    int wm0 = (wid & 1) * 64;                    // warp M offset
    int wn0 = (wid >> 1) * 32;                   // warp N offset
    int grp = lane >> 2;                         // 0..7
    int qid = lane & 3;                          // 0..3

    const float* Ab = A + (long)m0 * lda;
    const float* Bb = B + (long)n0 * ldb;

    // cp.async tile loader: chunk c into stage s
    auto issue = [&](int c, int s) {
        int k0 = c * TBK;
#pragma unroll
        for (int i = 0; i < 2; i++) {
            int idx = tid + 256 * i;             // 0..511
            int row = idx >> 2;                  // 0..127
            int cc = idx & 3;                    // 16B chunk within 64B row
            cp_async16(smem_u32(&sA[s][row][cc * 4]), Ab + (long)row * lda + k0 + cc * 4);
            cp_async16(smem_u32(&sB[s][row][cc * 4]), Bb + (long)row * ldb + k0 + cc * 4);
        }
        CP_COMMIT();
    };

    float acc[4][4][4] = {};                     // [mi][ni][reg]

    issue(0, 0);
    issue(1, 1);

    for (int c = 0; c < nch; c++) {
        int s = c & 1;
        CP_WAIT1();
        __syncthreads();

#pragma unroll
        for (int ks = 0; ks < TBK; ks += 8) {
            uint32_t a[4][4];
#pragma unroll
            for (int mi = 0; mi < 4; mi++) {
                int r = wm0 + mi * 16 + grp;
                a[mi][0] = f2tf32(sA[s][r    ][ks + qid]);
                a[mi][1] = f2tf32(sA[s][r + 8][ks + qid]);
                a[mi][2] = f2tf32(sA[s][r    ][ks + qid + 4]);
                a[mi][3] = f2tf32(sA[s][r + 8][ks + qid + 4]);
            }
            uint32_t b[4][2];
#pragma unroll
            for (int ni = 0; ni < 4; ni++) {
                int n = wn0 + ni * 8 + grp;
                b[ni][0] = f2tf32(sB[s][n][ks + qid]);
                b[ni][1] = f2tf32(sB[s][n][ks + qid + 4]);
            }
#pragma unroll
            for (int mi = 0; mi < 4; mi++)
#pragma unroll
                for (int ni = 0; ni < 4; ni++)
                    mma_tf32(acc[mi][ni], a[mi], b[ni]);
        }
        __syncthreads();
        if (c + 2 < nch) issue(c + 2, s);
    }

    // epilogue: fragment layout -> global (2 contiguous floats per reg pair)
#pragma unroll
    for (int mi = 0; mi < 4; mi++) {
#pragma unroll
        for (int ni = 0; ni < 4; ni++) {
            int row = m0 + wm0 + mi * 16 + grp;
            int col = n0 + wn0 + ni * 8 + 2 * qid;
            float2 v0 = make_float2(acc[mi][ni][0] * alpha, acc[mi][ni][1] * alpha);
            float2 v1 = make_float2(acc[mi][ni][2] * alpha, acc[mi][ni][3] * alpha);
            *(float2*)(C + (long)row * ldc + col) = v0;
            *(float2*)(C + (long)(row + 8) * ldc + col) = v1;
        }
    }
}

// ---------------- RoPE table (fp32 angle, fp64 sincos) ----------------
__global__ void rope_table_kernel(float* cosT, float* sinT) {
    int s = blockIdx.x;
    int i = threadIdx.x;
    float inv = (float)pow(10000.0, -(double)(2 * i) / (double)HD);
    float ang = (float)s * inv;
    double a = (double)ang;
    cosT[s * HALF_HD + i] = (float)cos(a);
    sinT[s * HALF_HD + i] = (float)sin(a);
}

// ---------------- RoPE apply + transpose ----------------
__global__ void rope_q_kernel(const float* __restrict__ qlin, const float* __restrict__ cosT,
                              const float* __restrict__ sinT, float* __restrict__ Q) {
    long idx = (long)blockIdx.x * blockDim.x + threadIdx.x;
    if (idx >= (long)BATCH * SEQ * NH * HALF_HD) return;
    int i = idx & (HALF_HD - 1);
    long t = idx >> 6;
    int h = t & (NH - 1); t >>= 4;
    int s = t & (SEQ - 1);
    int b = (int)(t >> 11);
    const float* src = qlin + ((long)(b * SEQ + s)) * DIM + h * HD + 2 * i;
    float xr = src[0], xi = src[1];
    float c = cosT[s * HALF_HD + i], sn = sinT[s * HALF_HD + i];
    float* dst = Q + (((long)(b * NH + h) * SEQ + s)) * HD + 2 * i;
    dst[0] = xr * c - xi * sn;
    dst[1] = xr * sn + xi * c;
}

__global__ void rope_k_kernel(const float* __restrict__ klin, const float* __restrict__ cosT,
                              const float* __restrict__ sinT, float* __restrict__ K) {
    long idx = (long)blockIdx.x * blockDim.x + threadIdx.x;
    if (idx >= (long)BATCH * SEQ * NKV * HALF_HD) return;
    int i = idx & (HALF_HD - 1);
    long t = idx >> 6;
    int h = t & (NKV - 1); t >>= 3;
    int s = t & (SEQ - 1);
    int b = (int)(t >> 11);
    const float* src = klin + ((long)(b * SEQ + s)) * (NKV * HD) + h * HD + 2 * i;
    float xr = src[0], xi = src[1];
    float c = cosT[s * HALF_HD + i], sn = sinT[s * HALF_HD + i];
    float* dst = K + (((long)(b * NKV + h) * SEQ + s)) * HD + 2 * i;
    dst[0] = xr * c - xi * sn;
    dst[1] = xr * sn + xi * c;
}

// V transpose: vlin[b,s,h,d] -> Vt[b,h,d,s]
__global__ void v_transpose_kernel(const float* __restrict__ vlin, float* __restrict__ Vt) {
    __shared__ float t[32][33];
    int bh = blockIdx.z;
    int b = bh >> 3, h = bh & 7;
    int s0 = blockIdx.x * 32, d0 = blockIdx.y * 32;
    int tx = threadIdx.x, ty = threadIdx.y;
    for (int i = ty; i < 32; i += 8)
        t[i][tx] = vlin[((long)(b * SEQ + s0 + i)) * (NKV * HD) + h * HD + d0 + tx];
    __syncthreads();
    for (int i = ty; i < 32; i += 8)
        Vt[((long)bh * HD + d0 + i) * SEQ + s0 + tx] = t[tx][i];
}

// ---------------- causal softmax ----------------
__global__ __launch_bounds__(256) void softmax_causal_kernel(float* __restrict__ scores) {
    long row = blockIdx.x;
    int qi = (int)(row & (SEQ - 1));
    float* p = scores + (row << 11);
    int len = qi + 1;
    int tid = threadIdx.x;

    float v[8];
    int cnt = 0;
    float m = -1e30f;
    for (int j = tid; j < len; j += 256) {
        float x = p[j];
        v[cnt++] = x;
        m = fmaxf(m, x);
    }
    __shared__ float sred[8];
#pragma unroll
    for (int o = 16; o > 0; o >>= 1) m = fmaxf(m, __shfl_xor_sync(0xffffffffu, m, o));
    if ((tid & 31) == 0) sred[tid >> 5] = m;
    __syncthreads();
    float bm = fmaxf(fmaxf(fmaxf(sred[0], sred[1]), fmaxf(sred[2], sred[3])),
                     fmaxf(fmaxf(sred[4], sred[5]), fmaxf(sred[6], sred[7])));
    __syncthreads();

    float s = 0.f;
    for (int c = 0; c < cnt; c++) { v[c] = expf(v[c] - bm); s += v[c]; }
#pragma unroll
    for (int o = 16; o > 0; o >>= 1) s += __shfl_xor_sync(0xffffffffu, s, o);
    if ((tid & 31) == 0) sred[tid >> 5] = s;
    __syncthreads();
    float bs = sred[0] + sred[1] + sred[2] + sred[3] + sred[4] + sred[5] + sred[6] + sred[7];
    float inv = 1.0f / bs;

    int c2 = 0;
    for (int j = tid; j < SEQ; j += 256) {
        float o = 0.f;
        if (j < len) o = v[c2++] * inv;
        p[j] = o;
    }
}

// ---------------- launch ----------------
extern "C" void kernel_launch(void* const* d_in, const int* in_sizes, int n_in,
                              void* d_out, int out_size) {
    const float* x  = (const float*)d_in[0];
    const float* wq = (const float*)d_in[1];
    const float* wk = (const float*)d_in[2];
    const float* wv = (const float*)d_in[3];
    const float* wo = (const float*)d_in[4];
    float* out = (float*)d_out;

    float* qlin; cudaGetSymbolAddress((void**)&qlin, g_qlin);
    float* klin; cudaGetSymbolAddress((void**)&klin, g_klin);
    float* vlin; cudaGetSymbolAddress((void**)&vlin, g_vlin);
    float* Q;    cudaGetSymbolAddress((void**)&Q,    g_Q);
    float* Kd;   cudaGetSymbolAddress((void**)&Kd,   g_K);
    float* Vt;   cudaGetSymbolAddress((void**)&Vt,   g_Vt);
    float* sc;   cudaGetSymbolAddress((void**)&sc,   g_scores);
    float* at;   cudaGetSymbolAddress((void**)&at,   g_attn_t);
    float* cT;   cudaGetSymbolAddress((void**)&cT,   g_cosT);
    float* sT;   cudaGetSymbolAddress((void**)&sT,   g_sinT);

    // 1) RoPE table
    rope_table_kernel<<<SEQ, HALF_HD>>>(cT, sT);

    // 2) QKV projections
    mma_gemm<0><<<dim3(DIM / TBN, M_ROWS / TBM, 1), 256>>>(
        x, DIM, wq, DIM, qlin, DIM, DIM, 1.f, 0, 0, 0, 0, 0, 0, 1, 1);
    mma_gemm<0><<<dim3((NKV * HD) / TBN, M_ROWS / TBM, 1), 256>>>(
        x, DIM, wk, DIM, klin, NKV * HD, DIM, 1.f, 0, 0, 0, 0, 0, 0, 1, 1);
    mma_gemm<0><<<dim3((NKV * HD) / TBN, M_ROWS / TBM, 1), 256>>>(
        x, DIM, wv, DIM, vlin, NKV * HD, DIM, 1.f, 0, 0, 0, 0, 0, 0, 1, 1);

    // 3) RoPE + transposes
    {
        long nq = (long)BATCH * SEQ * NH * HALF_HD;
        rope_q_kernel<<<(unsigned)((nq + 255) / 256), 256>>>(qlin, cT, sT, Q);
        long nk = (long)BATCH * SEQ * NKV * HALF_HD;
        rope_k_kernel<<<(unsigned)((nk + 255) / 256), 256>>>(klin, cT, sT, Kd);
        v_transpose_kernel<<<dim3(SEQ / 32, HD / 32, BATCH * NKV), dim3(32, 8)>>>(vlin, Vt);
    }

    // 4) scores = Q @ K^T * scale (causal tile skip)
    {
        const float scale = 0.088388347648318447f;   // 1/sqrt(128)
        mma_gemm<1><<<dim3(SEQ / TBN, SEQ / TBM, BATCH * NH), 256>>>(
            Q, HD, Kd, HD, sc, SEQ, HD, scale,
            (long)NH * SEQ * HD, (long)SEQ * HD,
            (long)NKV * SEQ * HD, (long)SEQ * HD,
            (long)NH * SEQ * SEQ, (long)SEQ * SEQ, NH, NREP);
    }

    // 5) causal softmax (writes zeros above diagonal)
    softmax_causal_kernel<<<BATCH * NH * SEQ, 256>>>(sc);

    // 6) attn_t = probs @ Vt^T  (K clipped by causality)
    mma_gemm<2><<<dim3(HD / TBN, SEQ / TBM, BATCH * NH), 256>>>(
        sc, SEQ, Vt, SEQ, at, DIM, SEQ, 1.f,
        (long)NH * SEQ * SEQ, (long)SEQ * SEQ,
        (long)NKV * HD * SEQ, (long)HD * SEQ,
        (long)SEQ * DIM, (long)HD, NH, NREP);

    // 7) out = attn_t @ wo^T
    mma_gemm<0><<<dim3(DIM / TBN, M_ROWS / TBM, 1), 256>>>(
        at, DIM, wo, DIM, out, DIM, DIM, 1.f, 0, 0, 0, 0, 0, 0, 1, 1);

    (void)in_sizes; (void)n_in; (void)out_size;
}

// round 6
// speedup vs baseline: 5.7156x; 1.1684x over previous
#include <cuda_runtime.h>
#include <cuda_bf16.h>
#include <cstdint>
#include <math.h>

// ---------------- problem constants ----------------
#define BATCH 2
#define SEQ   2048
#define DIM   2048
#define NH    16
#define NKV   8
#define HD    128
#define HALF_HD 64
#define M_ROWS (BATCH * SEQ)          // 4096

// 8-block permutation of the contraction dim: pos = (c&3)*2 | (c>>2)
// => positions (2q, 2q+1) hold original cols (q, q+4)  -> LDS.64 fragment loads
#define PERM8(c) ((((c) & 3) << 1) | ((c) >> 2))

// ---------------- scratch (static device globals; no allocation) ----------------
__device__ float g_xr[(size_t)M_ROWS * DIM];                   // x rounded, K-permuted
__device__ float g_wqkv[(size_t)(2 * DIM) * DIM];              // [wq;wk;wv] rounded, K-permuted (4096x2048)
__device__ float g_wor[(size_t)DIM * DIM];                     // wo rounded, K-permuted
__device__ float g_qkvlin[(size_t)M_ROWS * 2 * DIM];           // x @ wqkv^T  [4096, 4096] fp32
__device__ float g_Q[(size_t)BATCH * NH  * SEQ * HD];          // roped+scaled+rounded, d-permuted
__device__ float g_K[(size_t)BATCH * NKV * SEQ * HD];          // roped+rounded, d-permuted
__device__ float g_Vt[(size_t)BATCH * NKV * HD * SEQ];         // [B,KV,D,S] rounded, s-permuted
__device__ float g_at[(size_t)M_ROWS * DIM];                   // attn out rounded, col-permuted
__device__ float g_cosT[SEQ * HALF_HD];
__device__ float g_sinT[SEQ * HALF_HD];

// ---------------- PTX helpers ----------------
__device__ __forceinline__ uint32_t smem_u32(const void* p) {
    uint32_t a;
    asm("{ .reg .u64 t; cvta.to.shared.u64 t, %1; cvt.u32.u64 %0, t; }" : "=r"(a) : "l"(p));
    return a;
}
__device__ __forceinline__ float f2tf32f(float x) {
    uint32_t r;
    asm("cvt.rna.tf32.f32 %0, %1;" : "=r"(r) : "f"(x));
    return __uint_as_float(r);
}
__device__ __forceinline__ void cp_async16(uint32_t saddr, const void* g) {
    asm volatile("cp.async.cg.shared.global [%0], [%1], 16;" :: "r"(saddr), "l"(g));
}
#define CP_COMMIT() asm volatile("cp.async.commit_group;" ::: "memory")
#define CP_WAIT1()  asm volatile("cp.async.wait_group 1;" ::: "memory")

__device__ __forceinline__ void mma8(float* c, float a0, float a1, float a2, float a3,
                                     float b0, float b1) {
    asm volatile("mma.sync.aligned.m16n8k8.row.col.f32.tf32.tf32.f32 "
        "{%0,%1,%2,%3}, {%4,%5,%6,%7}, {%8,%9}, {%0,%1,%2,%3};"
        : "+f"(c[0]), "+f"(c[1]), "+f"(c[2]), "+f"(c[3])
        : "r"(__float_as_uint(a0)), "r"(__float_as_uint(a1)),
          "r"(__float_as_uint(a2)), "r"(__float_as_uint(a3)),
          "r"(__float_as_uint(b0)), "r"(__float_as_uint(b1)));
}

// ---------------- round + permute copy (tf32-rna, 8-block col perm) ----------------
__global__ void round_perm_kernel(const float* __restrict__ in, float* __restrict__ out, long n) {
    long i = (long)blockIdx.x * blockDim.x + threadIdx.x;
    if (i < n) out[(i & ~7L) | PERM8((int)(i & 7))] = f2tf32f(in[i]);
}

// ---------------- tf32 mma.sync GEMM (inputs pre-rounded + K-permuted) ----------------
// C[M,N] = A[M,K] @ B[N,K]^T
#define AROWA 24
#define AROWB 20

__global__ __launch_bounds__(256) void mma_gemm(
    const float* __restrict__ A, int lda,
    const float* __restrict__ B, int ldb,
    float* __restrict__ C, int ldc, int K)
{
    int m0 = blockIdx.y * 128;
    int n0 = blockIdx.x * 128;
    int nch = K / 16;

    __shared__ float sA[2][128][AROWA];
    __shared__ float sB[2][128][AROWB];

    int tid = threadIdx.x;
    int wid = tid >> 5;
    int lane = tid & 31;
    int wm0 = (wid & 1) * 64;
    int wn0 = (wid >> 1) * 32;
    int grp = lane >> 2;
    int qid = lane & 3;

    const float* Ab = A + (long)m0 * lda;
    const float* Bb = B + (long)n0 * ldb;

    auto issue = [&](int c, int s) {
        int k0 = c * 16;
#pragma unroll
        for (int i = 0; i < 2; i++) {
            int idx = tid + 256 * i;             // 0..511
            int row = idx >> 2;                  // 0..127
            int cc = idx & 3;
            cp_async16(smem_u32(&sA[s][row][cc * 4]), Ab + (long)row * lda + k0 + cc * 4);
            cp_async16(smem_u32(&sB[s][row][cc * 4]), Bb + (long)row * ldb + k0 + cc * 4);
        }
        CP_COMMIT();
    };

    float acc[4][4][4] = {};

    issue(0, 0);
    issue(1, 1);

    for (int c = 0; c < nch; c++) {
        int s = c & 1;
        CP_WAIT1();
        __syncthreads();

#pragma unroll
        for (int ks = 0; ks < 16; ks += 8) {
            float a[4][4];
#pragma unroll
            for (int mi = 0; mi < 4; mi++) {
                int r = wm0 + mi * 16 + grp;
                float2 x0 = *(const float2*)&sA[s][r][ks + qid * 2];
                float2 x1 = *(const float2*)&sA[s][r + 8][ks + qid * 2];
                a[mi][0] = x0.x; a[mi][1] = x1.x; a[mi][2] = x0.y; a[mi][3] = x1.y;
            }
            float b[4][2];
#pragma unroll
            for (int ni = 0; ni < 4; ni++) {
                float2 y = *(const float2*)&sB[s][wn0 + ni * 8 + grp][ks + qid * 2];
                b[ni][0] = y.x; b[ni][1] = y.y;
            }
#pragma unroll
            for (int mi = 0; mi < 4; mi++)
#pragma unroll
                for (int ni = 0; ni < 4; ni++)
                    mma8(acc[mi][ni], a[mi][0], a[mi][1], a[mi][2], a[mi][3], b[ni][0], b[ni][1]);
        }
        __syncthreads();
        if (c + 2 < nch) issue(c + 2, s);
    }

#pragma unroll
    for (int mi = 0; mi < 4; mi++) {
#pragma unroll
        for (int ni = 0; ni < 4; ni++) {
            int row = m0 + wm0 + mi * 16 + grp;
            int col = n0 + wn0 + ni * 8 + 2 * qid;
            *(float2*)(C + (long)row * ldc + col) = make_float2(acc[mi][ni][0], acc[mi][ni][1]);
            *(float2*)(C + (long)(row + 8) * ldc + col) = make_float2(acc[mi][ni][2], acc[mi][ni][3]);
        }
    }
}

// ---------------- flash attention (tf32 mma, causal, online softmax) ----------------
// Bq=128, Bk=64, 8 warps x 16 rows. Q pre-scaled; Q/K d-permuted; Vt key-permuted.
#define SQ_F (128 * 136)
#define SK_F (64 * 136)
#define SV_F (128 * 72)
#define SP_F (8 * 16 * 72)
#define FLASH_SMEM ((SQ_F + SK_F + SV_F + SP_F) * 4)

__global__ __launch_bounds__(256) void flash_kernel(
    const float* __restrict__ Q, const float* __restrict__ K,
    const float* __restrict__ Vt, float* __restrict__ at)
{
    extern __shared__ float sm[];
    float* sQ = sm;
    float* sK = sm + SQ_F;
    float* sV = sK + SK_F;

    int tid = threadIdx.x, wid = tid >> 5, lane = tid & 31;
    int grp = lane >> 2, qid = lane & 3;
    float* sP = sV + SV_F + wid * (16 * 72);

    int bh = blockIdx.y;
    int b = bh >> 4, h = bh & 15, kv = h >> 1;
    int qt = (int)gridDim.x - 1 - (int)blockIdx.x;     // big tiles first
    int qbase = qt * 128;
    const float* Qg = Q + (size_t)(b * NH + h) * SEQ * HD;
    const float* Kg = K + (size_t)(b * NKV + kv) * SEQ * HD;
    const float* Vg = Vt + (size_t)(b * NKV + kv) * HD * SEQ;

    // load Q tile (once)
#pragma unroll
    for (int i = 0; i < 16; i++) {
        int idx = tid + 256 * i;                 // 128 rows x 32 float4
        int row = idx >> 5, c4 = idx & 31;
        float4 v = *(const float4*)(Qg + (size_t)(qbase + row) * HD + c4 * 4);
        *(float4*)(sQ + row * 136 + c4 * 4) = v;
    }

    float o[16][4];
#pragma unroll
    for (int i = 0; i < 16; i++) { o[i][0] = o[i][1] = o[i][2] = o[i][3] = 0.f; }
    float m0 = -1e30f, m1 = -1e30f, l0 = 0.f, l1 = 0.f;

    int r0 = qbase + wid * 16 + grp;             // rows r0, r0+8
    int pp0 = PERM8(2 * qid), pp1 = PERM8(2 * qid + 1);
    int nkt = 2 * qt + 2;

    for (int kt = 0; kt < nkt; kt++) {
        __syncthreads();
        // fill K tile: 64 rows x 32 float4
#pragma unroll
        for (int i = 0; i < 8; i++) {
            int idx = tid + 256 * i;
            int row = idx >> 5, c4 = idx & 31;
            float4 v = *(const float4*)(Kg + (size_t)(kt * 64 + row) * HD + c4 * 4);
            *(float4*)(sK + row * 136 + c4 * 4) = v;
        }
        // fill V tile: 128 rows x 16 float4
#pragma unroll
        for (int i = 0; i < 8; i++) {
            int idx = tid + 256 * i;
            int row = idx >> 4, c4 = idx & 15;
            float4 v = *(const float4*)(Vg + (size_t)row * SEQ + kt * 64 + c4 * 4);
            *(float4*)(sV + row * 72 + c4 * 4) = v;
        }
        __syncthreads();

        if (kt * 64 > qbase + wid * 16 + 15) continue;   // whole warp masked this tile

        // ---- S = Q @ K^T (scale pre-folded into Q) ----
        float s[8][4];
#pragma unroll
        for (int ni = 0; ni < 8; ni++) { s[ni][0] = s[ni][1] = s[ni][2] = s[ni][3] = 0.f; }
        const float* q0 = sQ + (wid * 16 + grp) * 136 + qid * 2;
        const float* q1 = q0 + 8 * 136;
#pragma unroll
        for (int kk = 0; kk < 16; kk++) {
            float2 a02 = *(const float2*)(q0 + kk * 8);
            float2 a13 = *(const float2*)(q1 + kk * 8);
#pragma unroll
            for (int ni = 0; ni < 8; ni++) {
                float2 b01 = *(const float2*)(sK + (ni * 8 + grp) * 136 + kk * 8 + qid * 2);
                mma8(s[ni], a02.x, a13.x, a02.y, a13.y, b01.x, b01.y);
            }
        }

        // ---- causal mask ----
        if (kt * 64 + 63 > qbase + wid * 16) {
#pragma unroll
            for (int ni = 0; ni < 8; ni++) {
                int c0 = kt * 64 + ni * 8 + 2 * qid;
                if (c0 > r0)     s[ni][0] = -1e30f;
                if (c0 + 1 > r0) s[ni][1] = -1e30f;
                if (c0 > r0 + 8)     s[ni][2] = -1e30f;
                if (c0 + 1 > r0 + 8) s[ni][3] = -1e30f;
            }
        }

        // ---- online softmax (rows r0, r0+8; quad-lane reductions) ----
        float mx0 = -1e30f, mx1 = -1e30f;
#pragma unroll
        for (int ni = 0; ni < 8; ni++) {
            mx0 = fmaxf(mx0, fmaxf(s[ni][0], s[ni][1]));
            mx1 = fmaxf(mx1, fmaxf(s[ni][2], s[ni][3]));
        }
        mx0 = fmaxf(mx0, __shfl_xor_sync(0xffffffffu, mx0, 1));
        mx0 = fmaxf(mx0, __shfl_xor_sync(0xffffffffu, mx0, 2));
        mx1 = fmaxf(mx1, __shfl_xor_sync(0xffffffffu, mx1, 1));
        mx1 = fmaxf(mx1, __shfl_xor_sync(0xffffffffu, mx1, 2));
        float mn0 = fmaxf(m0, mx0), mn1 = fmaxf(m1, mx1);
        float al0 = __expf(m0 - mn0), al1 = __expf(m1 - mn1);
        m0 = mn0; m1 = mn1;
        float sum0 = 0.f, sum1 = 0.f;
#pragma unroll
        for (int ni = 0; ni < 8; ni++) {
            s[ni][0] = __expf(s[ni][0] - mn0); sum0 += s[ni][0];
            s[ni][1] = __expf(s[ni][1] - mn0); sum0 += s[ni][1];
            s[ni][2] = __expf(s[ni][2] - mn1); sum1 += s[ni][2];
            s[ni][3] = __expf(s[ni][3] - mn1); sum1 += s[ni][3];
        }
        sum0 += __shfl_xor_sync(0xffffffffu, sum0, 1);
        sum0 += __shfl_xor_sync(0xffffffffu, sum0, 2);
        sum1 += __shfl_xor_sync(0xffffffffu, sum1, 1);
        sum1 += __shfl_xor_sync(0xffffffffu, sum1, 2);
        l0 = l0 * al0 + sum0;
        l1 = l1 * al1 + sum1;
#pragma unroll
        for (int ni = 0; ni < 16; ni++) {
            o[ni][0] *= al0; o[ni][1] *= al0;
            o[ni][2] *= al1; o[ni][3] *= al1;
        }

        // ---- stage P (rounded, key-permuted) into warp-private SMEM ----
#pragma unroll
        for (int ni = 0; ni < 8; ni++) {
            sP[grp * 72 + ni * 8 + pp0]       = f2tf32f(s[ni][0]);
            sP[grp * 72 + ni * 8 + pp1]       = f2tf32f(s[ni][1]);
            sP[(grp + 8) * 72 + ni * 8 + pp0] = f2tf32f(s[ni][2]);
            sP[(grp + 8) * 72 + ni * 8 + pp1] = f2tf32f(s[ni][3]);
        }
        __syncwarp();

        // ---- O += P @ V ----
        float2 pa0[8], pa1[8];
#pragma unroll
        for (int kk = 0; kk < 8; kk++) {
            pa0[kk] = *(const float2*)(sP + grp * 72 + kk * 8 + qid * 2);
            pa1[kk] = *(const float2*)(sP + (grp + 8) * 72 + kk * 8 + qid * 2);
        }
#pragma unroll
        for (int ni = 0; ni < 16; ni++) {
#pragma unroll
            for (int kk = 0; kk < 8; kk++) {
                float2 b01 = *(const float2*)(sV + (ni * 8 + grp) * 72 + kk * 8 + qid * 2);
                mma8(o[ni], pa0[kk].x, pa1[kk].x, pa0[kk].y, pa1[kk].y, b01.x, b01.y);
            }
        }
        __syncwarp();
    }

    // ---- epilogue: normalize, round, store (col-permuted for out proj) ----
    float inv0 = 1.f / l0, inv1 = 1.f / l1;
    float* a0p = at + (size_t)(b * SEQ + r0) * DIM + h * HD;
    float* a1p = at + (size_t)(b * SEQ + r0 + 8) * DIM + h * HD;
#pragma unroll
    for (int ni = 0; ni < 16; ni++) {
        a0p[ni * 8 + pp0] = f2tf32f(o[ni][0] * inv0);
        a0p[ni * 8 + pp1] = f2tf32f(o[ni][1] * inv0);
        a1p[ni * 8 + pp0] = f2tf32f(o[ni][2] * inv1);
        a1p[ni * 8 + pp1] = f2tf32f(o[ni][3] * inv1);
    }
}

// ---------------- RoPE table (fp32 angle, fp64 sincos) ----------------
__global__ void rope_table_kernel(float* cosT, float* sinT) {
    int s = blockIdx.x;
    int i = threadIdx.x;
    float inv = (float)pow(10000.0, -(double)(2 * i) / (double)HD);
    float ang = (float)s * inv;
    double a = (double)ang;
    cosT[s * HALF_HD + i] = (float)cos(a);
    sinT[s * HALF_HD + i] = (float)sin(a);
}

// ---------------- RoPE apply + transpose (+scale for Q) + round + d-perm ----------------
__global__ void rope_q_kernel(const float* __restrict__ qkvlin, const float* __restrict__ cosT,
                              const float* __restrict__ sinT, float* __restrict__ Q) {
    long idx = (long)blockIdx.x * blockDim.x + threadIdx.x;
    if (idx >= (long)BATCH * SEQ * NH * HALF_HD) return;
    int i = idx & (HALF_HD - 1);
    long t = idx >> 6;
    int h = t & (NH - 1); t >>= 4;
    int s = t & (SEQ - 1);
    int b = (int)(t >> 11);
    const float* src = qkvlin + ((long)(b * SEQ + s)) * (2 * DIM) + h * HD + 2 * i;
    float xr = src[0], xi = src[1];
    float c = cosT[s * HALF_HD + i], sn = sinT[s * HALF_HD + i];
    const float scale = 0.088388347648318447f;   // 1/sqrt(128)
    float* dst = Q + (((long)(b * NH + h) * SEQ + s)) * HD;
    int cr = 2 * i, ci = 2 * i + 1;
    dst[(cr & ~7) | PERM8(cr & 7)] = f2tf32f(scale * (xr * c - xi * sn));
    dst[(ci & ~7) | PERM8(ci & 7)] = f2tf32f(scale * (xr * sn + xi * c));
}

__global__ void rope_k_kernel(const float* __restrict__ qkvlin, const float* __restrict__ cosT,
                              const float* __restrict__ sinT, float* __restrict__ K) {
    long idx = (long)blockIdx.x * blockDim.x + threadIdx.x;
    if (idx >= (long)BATCH * SEQ * NKV * HALF_HD) return;
    int i = idx & (HALF_HD - 1);
    long t = idx >> 6;
    int h = t & (NKV - 1); t >>= 3;
    int s = t & (SEQ - 1);
    int b = (int)(t >> 11);
    const float* src = qkvlin + ((long)(b * SEQ + s)) * (2 * DIM) + DIM + h * HD + 2 * i;
    float xr = src[0], xi = src[1];
    float c = cosT[s * HALF_HD + i], sn = sinT[s * HALF_HD + i];
    float* dst = K + (((long)(b * NKV + h) * SEQ + s)) * HD;
    int cr = 2 * i, ci = 2 * i + 1;
    dst[(cr & ~7) | PERM8(cr & 7)] = f2tf32f(xr * c - xi * sn);
    dst[(ci & ~7) | PERM8(ci & 7)] = f2tf32f(xr * sn + xi * c);
}

// V transpose: qkvlin v-part [b,s,h,d] -> Vt[b,h,d,s'] (rounded, s 8-block permuted)
// V columns live at [DIM + NKV*HD, 2*DIM) of qkvlin (fixed from 3*DIM bug).
__global__ void v_transpose_kernel(const float* __restrict__ qkvlin, float* __restrict__ Vt) {
    __shared__ float t[32][33];
    int bh = blockIdx.z;
    int b = bh >> 3, h = bh & 7;
    int s0 = blockIdx.x * 32, d0 = blockIdx.y * 32;
    int tx = threadIdx.x, ty = threadIdx.y;
    for (int i = ty; i < 32; i += 8)
        t[i][tx] = qkvlin[((long)(b * SEQ + s0 + i)) * (2 * DIM) + (DIM + NKV * HD) + h * HD + d0 + tx];
    __syncthreads();
    int sp = (tx & ~7) | PERM8(tx & 7);
    for (int i = ty; i < 32; i += 8)
        Vt[((long)bh * HD + d0 + i) * SEQ + s0 + sp] = f2tf32f(t[tx][i]);
}

// ---------------- launch ----------------
extern "C" void kernel_launch(void* const* d_in, const int* in_sizes, int n_in,
                              void* d_out, int out_size) {
    const float* x  = (const float*)d_in[0];
    const float* wq = (const float*)d_in[1];
    const float* wk = (const float*)d_in[2];
    const float* wv = (const float*)d_in[3];
    const float* wo = (const float*)d_in[4];
    float* out = (float*)d_out;

    float* xr;   cudaGetSymbolAddress((void**)&xr,   g_xr);
    float* wqkv; cudaGetSymbolAddress((void**)&wqkv, g_wqkv);
    float* wor;  cudaGetSymbolAddress((void**)&wor,  g_wor);
    float* qkvl; cudaGetSymbolAddress((void**)&qkvl, g_qkvlin);
    float* Q;    cudaGetSymbolAddress((void**)&Q,    g_Q);
    float* Kd;   cudaGetSymbolAddress((void**)&Kd,   g_K);
    float* Vt;   cudaGetSymbolAddress((void**)&Vt,   g_Vt);
    float* at;   cudaGetSymbolAddress((void**)&at,   g_at);
    float* cT;   cudaGetSymbolAddress((void**)&cT,   g_cosT);
    float* sT;   cudaGetSymbolAddress((void**)&sT,   g_sinT);

    cudaFuncSetAttribute(flash_kernel, cudaFuncAttributeMaxDynamicSharedMemorySize, FLASH_SMEM);

    // 0) round+permute inputs; concat wq/wk/wv
    {
        long nx = (long)M_ROWS * DIM;
        round_perm_kernel<<<(unsigned)((nx + 255) / 256), 256>>>(x, xr, nx);
        long nw = (long)DIM * DIM;               // wq: 2048x2048
        long nk = (long)(NKV * HD) * DIM;        // wk/wv: 1024x2048
        round_perm_kernel<<<(unsigned)((nw + 255) / 256), 256>>>(wq, wqkv, nw);
        round_perm_kernel<<<(unsigned)((nk + 255) / 256), 256>>>(wk, wqkv + (long)DIM * DIM, nk);
        round_perm_kernel<<<(unsigned)((nk + 255) / 256), 256>>>(wv, wqkv + (long)(DIM + NKV * HD) * DIM, nk);
        round_perm_kernel<<<(unsigned)((nw + 255) / 256), 256>>>(wo, wor, nw);
    }

    // 1) RoPE table
    rope_table_kernel<<<SEQ, HALF_HD>>>(cT, sT);

    // 2) fused QKV projection: qkvlin[4096,4096] = xr @ wqkv^T
    mma_gemm<<<dim3(2 * DIM / 128, M_ROWS / 128), 256>>>(
        xr, DIM, wqkv, DIM, qkvl, 2 * DIM, DIM);

    // 3) RoPE + transposes (round + permute outputs)
    {
        long nq = (long)BATCH * SEQ * NH * HALF_HD;
        rope_q_kernel<<<(unsigned)((nq + 255) / 256), 256>>>(qkvl, cT, sT, Q);
        long nk = (long)BATCH * SEQ * NKV * HALF_HD;
        rope_k_kernel<<<(unsigned)((nk + 255) / 256), 256>>>(qkvl, cT, sT, Kd);
        v_transpose_kernel<<<dim3(SEQ / 32, HD / 32, BATCH * NKV), dim3(32, 8)>>>(qkvl, Vt);
    }

    // 4) fused causal attention -> at
    flash_kernel<<<dim3(SEQ / 128, BATCH * NH), 256, FLASH_SMEM>>>(Q, Kd, Vt, at);

    // 5) out = at @ wo^T
    mma_gemm<<<dim3(DIM / 128, M_ROWS / 128), 256>>>(
        at, DIM, wor, DIM, out, DIM, DIM);

    (void)in_sizes; (void)n_in; (void)out_size;
}